// round 2
// baseline (speedup 1.0000x reference)
#include <cuda_runtime.h>
#include <cuda_bf16.h>

#define D 64
#define MAXN 100000
#define MAXE 1200000
#define EPS 1e-12f

// Scratch (device globals — no allocation allowed in kernel_launch)
__device__ float g_nh[(size_t)MAXN * D];   // normalized features, 25.6 MB (L2-resident)
__device__ float g_w[MAXE];                // per-edge exp weights
__device__ float g_psum[MAXN];             // per-dst softmax denominator

// ---------------------------------------------------------------------------
// K1: L2-normalize each node's feature row (one warp per node, float2/lane),
//     and zero psum for the softmax denominator pass.
// ---------------------------------------------------------------------------
__global__ void k_norm(const float* __restrict__ feat, int N) {
    int warp = (blockIdx.x * blockDim.x + threadIdx.x) >> 5;
    int lane = threadIdx.x & 31;
    if (warp >= N) return;
    const float2* f2 = (const float2*)(feat + (size_t)warp * D);
    float2 v = f2[lane];
    float ss = v.x * v.x + v.y * v.y;
    #pragma unroll
    for (int o = 16; o; o >>= 1) ss += __shfl_xor_sync(0xffffffffu, ss, o);
    float inv = 1.0f / fmaxf(sqrtf(ss), EPS);
    float2* o2 = (float2*)(g_nh + (size_t)warp * D);
    o2[lane] = make_float2(v.x * inv, v.y * inv);
    if (lane == 0) g_psum[warp] = 0.0f;
}

// ---------------------------------------------------------------------------
// K2: per-edge unnormalized softmax weight.
//     16 threads per edge; each thread loads one float4 of nh[src] and
//     nh[dst] (gathers hit L2: nh is 25.6MB, fits in 126MB L2), butterfly
//     shfl reduction over the 16-lane group, then w = exp(beta * dot).
//     Softmax is shift-invariant, so the reference's segment_max pass is
//     skipped: |beta*dot| <= |beta|*1 so exp() is numerically safe.
// ---------------------------------------------------------------------------
__global__ void k_edge_w(const int* __restrict__ src, const int* __restrict__ dst,
                         const float* __restrict__ beta, int E) {
    int t = blockIdx.x * blockDim.x + threadIdx.x;
    int e = t >> 4;
    int sub = t & 15;
    if (e >= E) return;
    int s = __ldg(src + e), d = __ldg(dst + e);
    float4 a = __ldg((const float4*)(g_nh + (size_t)s * D) + sub);
    float4 b = __ldg((const float4*)(g_nh + (size_t)d * D) + sub);
    float p = a.x * b.x + a.y * b.y + a.z * b.z + a.w * b.w;
    #pragma unroll
    for (int o = 8; o; o >>= 1) p += __shfl_xor_sync(0xffffffffu, p, o);
    if (sub == 0) {
        float w = __expf(__ldg(beta) * p);
        g_w[e] = w;
        atomicAdd(&g_psum[d], w);
    }
}

// ---------------------------------------------------------------------------
// K3: weighted scatter-aggregate. 16 threads per edge; each thread handles
//     4 contiguous dims. Uses red.global.add.v4.f32 (sm_90+) — fire-and-
//     forget vectorized L2 reduction, no return round-trip, 1/4 the
//     instruction count of scalar atomicAdd.
// ---------------------------------------------------------------------------
__global__ void k_agg(const float* __restrict__ feat,
                      const int* __restrict__ src, const int* __restrict__ dst,
                      float* __restrict__ out, int E) {
    int t = blockIdx.x * blockDim.x + threadIdx.x;
    int e = t >> 4;
    int sub = t & 15;
    if (e >= E) return;
    int s = __ldg(src + e), d = __ldg(dst + e);
    float p = g_w[e] / fmaxf(g_psum[d], EPS);
    float4 v = __ldg((const float4*)(feat + (size_t)s * D) + sub);
    float* addr = out + (size_t)d * D + sub * 4;
    asm volatile("red.global.add.v4.f32 [%0], {%1, %2, %3, %4};"
                 :: "l"(addr), "f"(v.x * p), "f"(v.y * p), "f"(v.z * p), "f"(v.w * p)
                 : "memory");
}

// ---------------------------------------------------------------------------
extern "C" void kernel_launch(void* const* d_in, const int* in_sizes, int n_in,
                              void* d_out, int out_size) {
    const float* feat = (const float*)d_in[0];
    const float* beta = (const float*)d_in[1];
    const int*   src  = (const int*)d_in[2];
    const int*   dst  = (const int*)d_in[3];
    float*       out  = (float*)d_out;

    int N = in_sizes[0] / D;
    int E = in_sizes[2];

    // d_out is poisoned; aggregation accumulates into it, so zero first.
    cudaMemsetAsync(out, 0, (size_t)out_size * sizeof(float));

    k_norm<<<(N + 7) / 8, 256>>>(feat, N);

    int edge_threads = E * 16;
    int blocks = (edge_threads + 255) / 256;
    k_edge_w<<<blocks, 256>>>(src, dst, beta, E);
    k_agg<<<blocks, 256>>>(feat, src, dst, out, E);
}

// round 3
// speedup vs baseline: 1.6871x; 1.6871x over previous
#include <cuda_runtime.h>
#include <cuda_fp16.h>

#define D 64
#define MAXN 100000
#define MAXE 1200000
#define EPS 1e-12f

// Scratch (device globals — no allocation allowed in kernel_launch)
__device__ __half g_nh[(size_t)MAXN * D];  // normalized features, fp16, 12.8 MB
__device__ float  g_psum[MAXN];            // per-dst softmax denominator

// ---------------------------------------------------------------------------
// K1: L2-normalize each node's row. 16 lanes per node, float4 per lane
//     (a full warp covers 2 nodes = 512B contiguous, perfectly coalesced).
//     Output stored fp16 (halves write traffic + halves edge-pass gathers).
//     Also zeroes psum.
// ---------------------------------------------------------------------------
__global__ void k_norm(const float* __restrict__ feat, int N) {
    int t = blockIdx.x * blockDim.x + threadIdx.x;
    int node = t >> 4;
    int sub = t & 15;
    if (node >= N) return;
    float4 v = __ldg((const float4*)(feat + (size_t)node * D) + sub);
    float ss = v.x * v.x + v.y * v.y + v.z * v.z + v.w * v.w;
    #pragma unroll
    for (int o = 8; o; o >>= 1) ss += __shfl_xor_sync(0xffffffffu, ss, o);
    float inv = 1.0f / fmaxf(sqrtf(ss), EPS);
    __half2 h0 = __floats2half2_rn(v.x * inv, v.y * inv);
    __half2 h1 = __floats2half2_rn(v.z * inv, v.w * inv);
    uint2 packed = make_uint2(*(const unsigned*)&h0, *(const unsigned*)&h1);
    ((uint2*)(g_nh + (size_t)node * D))[sub] = packed;
    if (sub == 0) g_psum[node] = 0.0f;
}

// ---------------------------------------------------------------------------
// K2 (fused edge pass): per edge, 16 lanes.
//     - gather 8B of fp16 nh[src] + nh[dst] per lane (128B/row, L2-resident)
//     - butterfly dot over the 16-lane group
//     - w = exp(beta * dot)   (softmax max-pass skipped: |beta*cos| <= |beta|)
//     - accumulate w into psum[dst]           (red.global.add.f32, lane 0)
//     - accumulate w*feat[src] into out[dst]  (red.global.add.v4.f32)
//     The softmax division is algebraically hoisted to K3:
//       out_i = (sum_j w_ij feat_j) / (sum_j w_ij)
// ---------------------------------------------------------------------------
__global__ void k_edge(const float* __restrict__ feat,
                       const int* __restrict__ src, const int* __restrict__ dst,
                       const float* __restrict__ beta,
                       float* __restrict__ out, int E) {
    int t = blockIdx.x * blockDim.x + threadIdx.x;
    int e = t >> 4;
    int sub = t & 15;
    if (e >= E) return;
    int s = __ldg(src + e), d = __ldg(dst + e);

    uint2 pa = __ldg((const uint2*)(g_nh + (size_t)s * D) + sub);
    uint2 pb = __ldg((const uint2*)(g_nh + (size_t)d * D) + sub);
    float2 a0 = __half22float2(*(const __half2*)&pa.x);
    float2 a1 = __half22float2(*(const __half2*)&pa.y);
    float2 b0 = __half22float2(*(const __half2*)&pb.x);
    float2 b1 = __half22float2(*(const __half2*)&pb.y);
    float p = a0.x * b0.x + a0.y * b0.y + a1.x * b1.x + a1.y * b1.y;
    #pragma unroll
    for (int o = 8; o; o >>= 1) p += __shfl_xor_sync(0xffffffffu, p, o);

    float w = __expf(__ldg(beta) * p);

    float4 v = __ldg((const float4*)(feat + (size_t)s * D) + sub);
    float* addr = out + (size_t)d * D + sub * 4;
    asm volatile("red.global.add.v4.f32 [%0], {%1, %2, %3, %4};"
                 :: "l"(addr), "f"(v.x * w), "f"(v.y * w), "f"(v.z * w), "f"(v.w * w)
                 : "memory");
    if (sub == 0) {
        asm volatile("red.global.add.f32 [%0], %1;"
                     :: "l"(&g_psum[d]), "f"(w) : "memory");
    }
}

// ---------------------------------------------------------------------------
// K3: per-node normalization: out[i] /= max(psum[i], EPS).
//     Isolated nodes: psum=0 and out row=0 -> stays 0 (matches reference).
// ---------------------------------------------------------------------------
__global__ void k_div(float* __restrict__ out, int N) {
    int t = blockIdx.x * blockDim.x + threadIdx.x;
    int node = t >> 4;
    int sub = t & 15;
    if (node >= N) return;
    float inv = 1.0f / fmaxf(g_psum[node], EPS);
    float4* p = (float4*)(out + (size_t)node * D) + sub;
    float4 v = *p;
    v.x *= inv; v.y *= inv; v.z *= inv; v.w *= inv;
    *p = v;
}

// ---------------------------------------------------------------------------
extern "C" void kernel_launch(void* const* d_in, const int* in_sizes, int n_in,
                              void* d_out, int out_size) {
    const float* feat = (const float*)d_in[0];
    const float* beta = (const float*)d_in[1];
    const int*   src  = (const int*)d_in[2];
    const int*   dst  = (const int*)d_in[3];
    float*       out  = (float*)d_out;

    int N = in_sizes[0] / D;
    int E = in_sizes[2];

    // out accumulates via red.add, so it must start at zero.
    cudaMemsetAsync(out, 0, (size_t)out_size * sizeof(float));

    int node_threads = N * 16;
    k_norm<<<(node_threads + 255) / 256, 256>>>(feat, N);

    int edge_threads = E * 16;
    k_edge<<<(edge_threads + 255) / 256, 256>>>(feat, src, dst, beta, out, E);

    k_div<<<(node_threads + 255) / 256, 256>>>(out, N);
}

// round 4
// speedup vs baseline: 1.8092x; 1.0723x over previous
#include <cuda_runtime.h>
#include <cuda_fp16.h>

#define D 64
#define MAXN 100000
#define MAXE 1200000
#define EPS 1e-12f

// Scratch (device globals — no allocation allowed in kernel_launch)
__device__ __half g_nh[(size_t)MAXN * D];  // normalized features, fp16, 12.8 MB
__device__ float  g_norm[MAXN];            // per-node L2 norm, 400 KB
__device__ float  g_psum[MAXN];            // per-dst softmax denominator

// ---------------------------------------------------------------------------
// K1: L2-normalize each node's row. 16 lanes per node, float4 per lane
//     (a full warp covers 2 nodes = 512B contiguous, perfectly coalesced).
//     Stores nh in fp16 AND the norm scalar, so the edge pass can
//     reconstruct feat = norm * nh without re-gathering fp32 feat.
//     Also zeroes psum.
// ---------------------------------------------------------------------------
__global__ void k_norm(const float* __restrict__ feat, int N) {
    int t = blockIdx.x * blockDim.x + threadIdx.x;
    int node = t >> 4;
    int sub = t & 15;
    if (node >= N) return;
    float4 v = __ldg((const float4*)(feat + (size_t)node * D) + sub);
    float ss = v.x * v.x + v.y * v.y + v.z * v.z + v.w * v.w;
    #pragma unroll
    for (int o = 8; o; o >>= 1) ss += __shfl_xor_sync(0xffffffffu, ss, o);
    float nrm = fmaxf(sqrtf(ss), EPS);
    float inv = 1.0f / nrm;
    __half2 h0 = __floats2half2_rn(v.x * inv, v.y * inv);
    __half2 h1 = __floats2half2_rn(v.z * inv, v.w * inv);
    uint2 packed = make_uint2(*(const unsigned*)&h0, *(const unsigned*)&h1);
    ((uint2*)(g_nh + (size_t)node * D))[sub] = packed;
    if (sub == 0) {
        g_norm[node] = nrm;
        g_psum[node] = 0.0f;
    }
}

// ---------------------------------------------------------------------------
// K2 (fused edge pass): per edge, 16 lanes.
//     - gather 8B of fp16 nh[src] + nh[dst] per lane (128B/row, L2-resident)
//     - butterfly dot over the 16-lane group
//     - w = exp(beta * dot)   (softmax max-pass skipped: shift-invariant,
//       |beta*cos| <= |beta| so exp is safe)
//     - message reconstructed from registers: feat[src] = norm[src]*nh[src]
//       -> NO fp32 feat gather (saves 256B/edge of L2 traffic)
//     - accumulate w*feat[src] into out[dst]  (red.global.add.v4.f32)
//     - accumulate w into psum[dst]           (red.global.add.f32, lane 0)
//     Softmax division hoisted to K3: out_i = (sum w*feat) / (sum w).
// ---------------------------------------------------------------------------
__global__ void k_edge(const int* __restrict__ src, const int* __restrict__ dst,
                       const float* __restrict__ beta,
                       float* __restrict__ out, int E) {
    int t = blockIdx.x * blockDim.x + threadIdx.x;
    int e = t >> 4;
    int sub = t & 15;
    if (e >= E) return;
    int s = __ldg(src + e), d = __ldg(dst + e);

    uint2 pa = __ldg((const uint2*)(g_nh + (size_t)s * D) + sub);
    uint2 pb = __ldg((const uint2*)(g_nh + (size_t)d * D) + sub);
    float2 a0 = __half22float2(*(const __half2*)&pa.x);
    float2 a1 = __half22float2(*(const __half2*)&pa.y);
    float2 b0 = __half22float2(*(const __half2*)&pb.x);
    float2 b1 = __half22float2(*(const __half2*)&pb.y);
    float p = a0.x * b0.x + a0.y * b0.y + a1.x * b1.x + a1.y * b1.y;
    #pragma unroll
    for (int o = 8; o; o >>= 1) p += __shfl_xor_sync(0xffffffffu, p, o);

    float w = __expf(__ldg(beta) * p);
    float wn = w * __ldg(&g_norm[s]);   // w * norm[src]: message scale

    float* addr = out + (size_t)d * D + sub * 4;
    asm volatile("red.global.add.v4.f32 [%0], {%1, %2, %3, %4};"
                 :: "l"(addr), "f"(a0.x * wn), "f"(a0.y * wn),
                    "f"(a1.x * wn), "f"(a1.y * wn)
                 : "memory");
    if (sub == 0) {
        asm volatile("red.global.add.f32 [%0], %1;"
                     :: "l"(&g_psum[d]), "f"(w) : "memory");
    }
}

// ---------------------------------------------------------------------------
// K3: per-node normalization: out[i] /= max(psum[i], EPS).
//     Isolated nodes: psum=0 and out row=0 -> stays 0 (matches reference).
// ---------------------------------------------------------------------------
__global__ void k_div(float* __restrict__ out, int N) {
    int t = blockIdx.x * blockDim.x + threadIdx.x;
    int node = t >> 4;
    int sub = t & 15;
    if (node >= N) return;
    float inv = 1.0f / fmaxf(g_psum[node], EPS);
    float4* p = (float4*)(out + (size_t)node * D) + sub;
    float4 v = *p;
    v.x *= inv; v.y *= inv; v.z *= inv; v.w *= inv;
    *p = v;
}

// ---------------------------------------------------------------------------
extern "C" void kernel_launch(void* const* d_in, const int* in_sizes, int n_in,
                              void* d_out, int out_size) {
    const float* feat = (const float*)d_in[0];
    const float* beta = (const float*)d_in[1];
    const int*   src  = (const int*)d_in[2];
    const int*   dst  = (const int*)d_in[3];
    float*       out  = (float*)d_out;

    int N = in_sizes[0] / D;
    int E = in_sizes[2];

    // out accumulates via red.add, so it must start at zero.
    cudaMemsetAsync(out, 0, (size_t)out_size * sizeof(float));

    int node_threads = N * 16;
    k_norm<<<(node_threads + 255) / 256, 256>>>(feat, N);

    int edge_threads = E * 16;
    k_edge<<<(edge_threads + 255) / 256, 256>>>(src, dst, beta, out, E);

    k_div<<<(node_threads + 255) / 256, 256>>>(out, N);
}